// round 15
// baseline (speedup 1.0000x reference)
#include <cuda_runtime.h>
#include <cuda_bf16.h>
#include <math.h>

// Problem constants
#define BATCH   64
#define SEQ     512
#define HID     256
#define NHEADS  4
#define HDIM    64
#define MROWS   (BATCH*SEQ)      // 32768
#define C_EXP   0.18033688011112042f   // 0.125 * log2(e)

// Scratch (alloc-free rule: __device__ globals)
__device__ unsigned g_Qt[(size_t)MROWS * HID];                // Q proj tf32, row-major
__device__ unsigned g_Kt[(size_t)MROWS * HID];                // K proj tf32, [B][H][S][64]
__device__ unsigned g_Vt[(size_t)BATCH * HDIM * SEQ];         // V^T per batch, tf32
__device__ unsigned g_Wt[2 * HID * HID + HID * HDIM];         // Wq^T, Wk^T, Wv^T tf32
__device__ unsigned g_WhT[HID * HDIM];                        // Wh^T tf32 [256][64]

__device__ __forceinline__ unsigned f2tf32(float x)
{
    unsigned o;
    asm("cvt.rna.tf32.f32 %0, %1;" : "=r"(o) : "f"(x));
    return o;
}

__device__ __forceinline__ void cp16(void* dst_smem, const void* src_gmem)
{
    unsigned s = (unsigned)__cvta_generic_to_shared(dst_smem);
    asm volatile("cp.async.cg.shared.global [%0], [%1], 16;" :: "r"(s), "l"(src_gmem));
}
__device__ __forceinline__ void cp_commit()
{
    asm volatile("cp.async.commit_group;");
}
__device__ __forceinline__ void cp_wait0()
{
    asm volatile("cp.async.wait_group 0;");
}

// ---------------------------------------------------------------------------
// All four weight transposes in ONE kernel. 160 blocks of 32x32 tiles.
// ---------------------------------------------------------------------------
__global__ void __launch_bounds__(256)
transpose_all_kernel(const float* __restrict__ Wq, const float* __restrict__ Wk,
                     const float* __restrict__ Wv, const float* __restrict__ Wh,
                     unsigned* __restrict__ dq, unsigned* __restrict__ dk,
                     unsigned* __restrict__ dv, unsigned* __restrict__ dh)
{
    __shared__ unsigned t[32][33];
    int id = blockIdx.x;
    const float* src; unsigned* dst; int K, N, lid;
    if (id < 64)       { src = Wq; dst = dq; K = 256; N = 256; lid = id; }
    else if (id < 128) { src = Wk; dst = dk; K = 256; N = 256; lid = id - 64; }
    else if (id < 144) { src = Wv; dst = dv; K = 256; N = 64;  lid = id - 128; }
    else               { src = Wh; dst = dh; K = 64;  N = 256; lid = id - 144; }
    int kt = K / 32;
    int k0 = (lid % kt) * 32;
    int n0 = (lid / kt) * 32;
    const int tx = threadIdx.x & 31;
    const int ty = threadIdx.x >> 5;

    #pragma unroll
    for (int i = 0; i < 4; i++) {
        int r = ty + i * 8;
        t[tx][r] = f2tf32(src[(size_t)(k0 + r) * N + n0 + tx]);
    }
    __syncthreads();
    #pragma unroll
    for (int i = 0; i < 4; i++) {
        int r = ty + i * 8;
        dst[(size_t)(n0 + r) * K + k0 + tx] = t[r][tx];
    }
}

// ---------------------------------------------------------------------------
// FUSED projection GEMMs: one launch covers Q, K, V. (round-12 version)
// ---------------------------------------------------------------------------
#define GS 36

__global__ void __launch_bounds__(256, 2)
gemm_fused_kernel(const float* __restrict__ Aq, const float* __restrict__ Ak,
                  const float* __restrict__ Av,
                  const unsigned* __restrict__ Wtq, const unsigned* __restrict__ Wtk,
                  const unsigned* __restrict__ Wtv,
                  const float* __restrict__ bq, const float* __restrict__ bk,
                  const float* __restrict__ bv,
                  unsigned* __restrict__ Qt, unsigned* __restrict__ Kt,
                  unsigned* __restrict__ Vt)
{
    extern __shared__ unsigned gsm[];
    unsigned* Asb[2] = { gsm, gsm + 128 * GS };
    unsigned* Wsb[2] = { gsm + 2 * 128 * GS, gsm + 2 * 128 * GS + 64 * GS };

    const int bx = blockIdx.x;
    const float* A; const unsigned* Wt; const float* bias; unsigned* Ct;
    int tout, n0;
    if (bx < 4)      { A = Aq; Wt = Wtq; bias = bq; Ct = Qt; tout = 2; n0 = bx * 64; }
    else if (bx < 8) { A = Ak; Wt = Wtk; bias = bk; Ct = Kt; tout = 3; n0 = (bx - 4) * 64; }
    else             { A = Av; Wt = Wtv; bias = bv; Ct = Vt; tout = 1; n0 = 0; }

    const int m0  = blockIdx.y * 128;
    const int tid = threadIdx.x;
    const int w   = tid >> 5;
    const int tx  = tid & 31;
    const int lane4 = tx & 3;
    const int wq    = tx >> 2;
    const int mb = (w & 3) * 32;
    const int nb = (w >> 2) * 32;

    const int lr  = tid >> 3;
    const int lc4 = (tid & 7) * 4;

    float4 areg[4];

    #define LDG_A(kc) do { \
        _Pragma("unroll") \
        for (int it = 0; it < 4; it++) \
            areg[it] = *reinterpret_cast<const float4*>( \
                &A[(size_t)(m0 + lr + it * 32) * 256 + (kc) * 32 + lc4]); \
    } while (0)
    #define STS_A(buf) do { \
        _Pragma("unroll") \
        for (int it = 0; it < 4; it++) \
            *reinterpret_cast<uint4*>(&Asb[buf][(lr + it * 32) * GS + lc4]) = \
                make_uint4(f2tf32(areg[it].x), f2tf32(areg[it].y), \
                           f2tf32(areg[it].z), f2tf32(areg[it].w)); \
    } while (0)
    #define CPW(kc, buf) do { \
        _Pragma("unroll") \
        for (int it = 0; it < 2; it++) \
            cp16(&Wsb[buf][(lr + it * 32) * GS + lc4], \
                 &Wt[(size_t)(n0 + lr + it * 32) * 256 + (kc) * 32 + lc4]); \
        cp_commit(); \
    } while (0)

    float acc[2][4][4];
    #pragma unroll
    for (int m = 0; m < 2; m++)
        #pragma unroll
        for (int n = 0; n < 4; n++)
            #pragma unroll
            for (int c = 0; c < 4; c++) acc[m][n][c] = 0.f;

    LDG_A(0);
    CPW(0, 0);
    STS_A(0);
    LDG_A(1);
    cp_wait0();
    __syncthreads();

    #pragma unroll 2
    for (int kc8 = 0; kc8 < 8; kc8++) {
        int cur = kc8 & 1;
        if (kc8 < 7) CPW(kc8 + 1, 1 - cur);

        unsigned* As = Asb[cur];
        unsigned* Ws = Wsb[cur];
        #pragma unroll
        for (int kk = 0; kk < 4; kk++) {
            unsigned a[2][4], bf[4][2];
            #pragma unroll
            for (int m = 0; m < 2; m++) {
                int row = mb + m * 16 + wq;
                int col = kk * 8 + lane4;
                a[m][0] = As[row * GS + col];
                a[m][1] = As[(row + 8) * GS + col];
                a[m][2] = As[row * GS + col + 4];
                a[m][3] = As[(row + 8) * GS + col + 4];
            }
            #pragma unroll
            for (int n = 0; n < 4; n++) {
                int nr = nb + n * 8 + wq;
                bf[n][0] = Ws[nr * GS + kk * 8 + lane4];
                bf[n][1] = Ws[nr * GS + kk * 8 + lane4 + 4];
            }
            #pragma unroll
            for (int m = 0; m < 2; m++)
                #pragma unroll
                for (int n = 0; n < 4; n++) {
                    float* d = acc[m][n];
                    asm volatile(
                        "mma.sync.aligned.m16n8k8.row.col.f32.tf32.tf32.f32 "
                        "{%0,%1,%2,%3}, {%4,%5,%6,%7}, {%8,%9}, {%0,%1,%2,%3};\n"
                        : "+f"(d[0]), "+f"(d[1]), "+f"(d[2]), "+f"(d[3])
                        : "r"(a[m][0]), "r"(a[m][1]), "r"(a[m][2]), "r"(a[m][3]),
                          "r"(bf[n][0]), "r"(bf[n][1]));
                }
        }

        if (kc8 < 7) {
            STS_A(1 - cur);
            if (kc8 < 6) LDG_A(kc8 + 2);
            cp_wait0();
            __syncthreads();
        }
    }

    if (tout == 2) {
        #pragma unroll
        for (int m = 0; m < 2; m++) {
            int row = m0 + mb + m * 16 + wq;
            #pragma unroll
            for (int n = 0; n < 4; n++) {
                int col = n0 + nb + n * 8 + lane4 * 2;
                float2 bb = *reinterpret_cast<const float2*>(&bias[col]);
                Ct[(size_t)row * HID + col]           = f2tf32(acc[m][n][0] + bb.x);
                Ct[(size_t)row * HID + col + 1]       = f2tf32(acc[m][n][1] + bb.y);
                Ct[(size_t)(row + 8) * HID + col]     = f2tf32(acc[m][n][2] + bb.x);
                Ct[(size_t)(row + 8) * HID + col + 1] = f2tf32(acc[m][n][3] + bb.y);
            }
        }
    } else if (tout == 3) {
        #pragma unroll
        for (int m = 0; m < 2; m++) {
            int r0 = m0 + mb + m * 16 + wq;
            int r1 = r0 + 8;
            int bb0 = r0 >> 9, s0 = r0 & 511, s1 = r1 & 511;
            #pragma unroll
            for (int n = 0; n < 4; n++) {
                int col = n0 + nb + n * 8 + lane4 * 2;
                int h = col >> 6, d = col & 63;
                size_t base = ((size_t)bb0 * NHEADS + h) * SEQ;
                float2 bb = *reinterpret_cast<const float2*>(&bias[col]);
                Ct[(base + s0) * HDIM + d]     = f2tf32(acc[m][n][0] + bb.x);
                Ct[(base + s0) * HDIM + d + 1] = f2tf32(acc[m][n][1] + bb.y);
                Ct[(base + s1) * HDIM + d]     = f2tf32(acc[m][n][2] + bb.x);
                Ct[(base + s1) * HDIM + d + 1] = f2tf32(acc[m][n][3] + bb.y);
            }
        }
    } else {
        #pragma unroll
        for (int m = 0; m < 2; m++) {
            int r0 = m0 + mb + m * 16 + wq;
            int r1 = r0 + 8;
            int b0 = r0 >> 9, s0 = r0 & 511;
            int s1 = r1 & 511;
            #pragma unroll
            for (int n = 0; n < 4; n++) {
                int col = n0 + nb + n * 8 + lane4 * 2;
                float2 bb = *reinterpret_cast<const float2*>(&bias[col]);
                Ct[((size_t)b0 * HDIM + col) * SEQ + s0]     = f2tf32(acc[m][n][0] + bb.x);
                Ct[((size_t)b0 * HDIM + col + 1) * SEQ + s0] = f2tf32(acc[m][n][1] + bb.y);
                Ct[((size_t)b0 * HDIM + col) * SEQ + s1]     = f2tf32(acc[m][n][2] + bb.x);
                Ct[((size_t)b0 * HDIM + col + 1) * SEQ + s1] = f2tf32(acc[m][n][3] + bb.y);
            }
        }
    }
    #undef LDG_A
    #undef STS_A
    #undef CPW
}

// ---------------------------------------------------------------------------
// Slim exp2: no clamp (inputs bounded), 2-op exponent reconstruction.
// ---------------------------------------------------------------------------
__device__ __forceinline__ float exp2s(float y)
{
    float t = y + 12582912.0f;
    float f = y - (t - 12582912.0f);
    float p = 0.0013333558f;
    p = fmaf(p, f, 0.0096181291f);
    p = fmaf(p, f, 0.0555041087f);
    p = fmaf(p, f, 0.2402265069f);
    p = fmaf(p, f, 0.6931471806f);
    p = fmaf(p, f, 1.0f);
    unsigned r = (__float_as_uint(t) << 23) + 0x3F800000u;
    return __uint_as_float(r) * p;
}

// ---------------------------------------------------------------------------
// Attention kernel v5: 16-row q-tile, 2 CTAs/SM (latency hiding across CTAs).
// 256 threads / 8 warps, __launch_bounds__(256,2). Per thread: acc[32]+att_acc[32].
// K staged as 4 chunks of 128 rows per head, cp.async double-buffered (phase
// counter ph = h*4+c picks buffer parity). Warp w owns k cols
// {nt*64 + w*8 : nt<8}; chunk c covers nt = 2c, 2c+1.
// acc id = nt*4 + rs*2 + p ; rows = rs*8 + wq ; cols = nt*64 + w*8 + lane4*2 + p.
// smem: Qs[16][260] + Ksb[2][128][68] + red[16][9] = 86848 B -> 2 CTAs/SM.
// ---------------------------------------------------------------------------
#define QS_ST 260
#define KS_ST 68

__global__ void __launch_bounds__(256, 2)
attn_kernel(const unsigned* __restrict__ Qt, const unsigned* __restrict__ Kt,
            const int* __restrict__ mask, float* __restrict__ att_out)
{
    extern __shared__ unsigned smu[];
    unsigned* Qs = smu;                              // [16][260]
    unsigned* Ksb[2] = { smu + 16 * QS_ST,
                         smu + 16 * QS_ST + 128 * KS_ST };   // 2 x [128][68]
    float* red = (float*)(smu + 16 * QS_ST + 2 * 128 * KS_ST);  // [16][9]

    const int b   = blockIdx.y;
    const int q0  = blockIdx.x * 16;
    const int tid = threadIdx.x;
    const int w   = tid >> 5;
    const int tx  = tid & 31;
    const int lane4 = tx & 3;
    const int wq    = tx >> 2;

    // prefetch head 0, chunk 0 (K rows 0..127) into buf 0
    {
        const unsigned* src = &Kt[((size_t)b * NHEADS * SEQ) * HDIM];
        #pragma unroll
        for (int it = 0; it < 8; it++) {
            int idx = it * 256 + tid;           // 2048 16B chunks
            int row = idx >> 4;
            int c4  = (idx & 15) * 4;
            cp16(&Ksb[0][row * KS_ST + c4], &src[row * HDIM + c4]);
        }
        cp_commit();
    }

    // Stage Q tile [16][256] (already tf32): 1024 uint4
    #pragma unroll
    for (int it = 0; it < 4; it++) {
        int idx = it * 256 + tid;
        int q   = idx >> 6;
        int c4  = (idx & 63) * 4;
        uint4 v = *reinterpret_cast<const uint4*>(
            &Qt[(size_t)(b * SEQ + q0 + q) * HID + c4]);
        *reinterpret_cast<uint4*>(&Qs[q * QS_ST + c4]) = v;
    }

    // Pack mask bits: bi = rs*16 + nt*2 + p ; row = rs*8 + wq
    unsigned mbits = 0u;
    #pragma unroll
    for (int rs = 0; rs < 2; rs++) {
        int row = rs * 8 + wq;
        const int* mrow = mask + ((size_t)b * SEQ + q0 + row) * SEQ;
        #pragma unroll
        for (int nt = 0; nt < 8; nt++) {
            int2 mv = *reinterpret_cast<const int2*>(&mrow[nt * 64 + w * 8 + lane4 * 2]);
            int bi = rs * 16 + nt * 2;
            mbits |= ((unsigned)(mv.x != 0)) << bi;
            mbits |= ((unsigned)(mv.y != 0)) << (bi + 1);
        }
    }

    float att_acc[32];
    #pragma unroll
    for (int i = 0; i < 32; i++) att_acc[i] = 0.f;

    cp_wait0();
    __syncthreads();

    float acc[32];

    #pragma unroll 1
    for (int h = 0; h < NHEADS; h++) {
        #pragma unroll
        for (int i = 0; i < 32; i++) acc[i] = 0.f;

        #pragma unroll 1
        for (int c = 0; c < 4; c++) {
            int ph  = h * 4 + c;
            int cur = ph & 1;
            if (ph < 15) {
                int nph = ph + 1;
                int nh = nph >> 2, nc = nph & 3;
                const unsigned* src =
                    &Kt[(((size_t)b * NHEADS + nh) * SEQ + nc * 128) * HDIM];
                #pragma unroll
                for (int it = 0; it < 8; it++) {
                    int idx = it * 256 + tid;
                    int row = idx >> 4;
                    int c4  = (idx & 15) * 4;
                    cp16(&Ksb[1 - cur][row * KS_ST + c4], &src[row * HDIM + c4]);
                }
                cp_commit();
            }

            unsigned* Ks = Ksb[cur];
            #pragma unroll
            for (int ks = 0; ks < 8; ks++) {
                int cb = h * 64 + ks * 8 + lane4;
                unsigned a0 = Qs[wq * QS_ST + cb];
                unsigned a1 = Qs[(wq + 8) * QS_ST + cb];
                unsigned a2 = Qs[wq * QS_ST + cb + 4];
                unsigned a3 = Qs[(wq + 8) * QS_ST + cb + 4];
                #pragma unroll
                for (int ntl = 0; ntl < 2; ntl++) {
                    int krow = ntl * 64 + w * 8 + wq;
                    unsigned b0 = Ks[krow * KS_ST + ks * 8 + lane4];
                    unsigned b1 = Ks[krow * KS_ST + ks * 8 + lane4 + 4];
                    float* d = &acc[(c * 2 + ntl) * 4];
                    asm volatile(
                        "mma.sync.aligned.m16n8k8.row.col.f32.tf32.tf32.f32 "
                        "{%0,%1,%2,%3}, {%4,%5,%6,%7}, {%8,%9}, {%0,%1,%2,%3};\n"
                        : "+f"(d[0]), "+f"(d[1]), "+f"(d[2]), "+f"(d[3])
                        : "r"(a0), "r"(a1), "r"(a2), "r"(a3),
                          "r"(b0), "r"(b1));
                }
            }
            if (ph < 15) {
                cp_wait0();
                __syncthreads();
            }
        }

        // -------- softmax: exp on raw bounded logits, mask-zero, sum --------
        float rsum[2];
        #pragma unroll
        for (int rs = 0; rs < 2; rs++) {
            float s = 0.f;
            #pragma unroll
            for (int nt = 0; nt < 8; nt++)
                #pragma unroll
                for (int p = 0; p < 2; p++) {
                    int id = nt * 4 + rs * 2 + p;
                    int bi = rs * 16 + nt * 2 + p;
                    float e = exp2s(acc[id] * C_EXP);
                    e = ((mbits >> bi) & 1u) ? e : 0.f;
                    acc[id] = e;
                    s += e;
                }
            s += __shfl_xor_sync(0xffffffffu, s, 1);
            s += __shfl_xor_sync(0xffffffffu, s, 2);
            rsum[rs] = s;
        }
        if (lane4 == 0) {
            #pragma unroll
            for (int rs = 0; rs < 2; rs++)
                red[(rs * 8 + wq) * 9 + w] = rsum[rs];
        }
        __syncthreads();
        #pragma unroll
        for (int rs = 0; rs < 2; rs++) {
            int row = rs * 8 + wq;
            float s = 0.f;
            #pragma unroll
            for (int ww = 0; ww < 8; ww++) s += red[row * 9 + ww];
            float inv = 0.25f / s;       // head-mean folded in
            #pragma unroll
            for (int nt = 0; nt < 8; nt++)
                #pragma unroll
                for (int p = 0; p < 2; p++) {
                    int id = nt * 4 + rs * 2 + p;
                    att_acc[id] += acc[id] * inv;
                }
        }
        // red next written only after next head's chunk syncs -> no extra sync
    }

    // Write attention [B, Sq, Sk]
    #pragma unroll
    for (int rs = 0; rs < 2; rs++) {
        int row = rs * 8 + wq;
        float* dst = att_out + ((size_t)b * SEQ + q0 + row) * SEQ;
        #pragma unroll
        for (int nt = 0; nt < 8; nt++) {
            int col = nt * 64 + w * 8 + lane4 * 2;
            *reinterpret_cast<float2*>(&dst[col]) =
                make_float2(att_acc[nt * 4 + rs * 2],
                            att_acc[nt * 4 + rs * 2 + 1]);
        }
    }
}

// ---------------------------------------------------------------------------
// ctx + out-proj, tf32 tensor cores (round-12 proven version, 2 CTAs/SM).
// ---------------------------------------------------------------------------
#define CTS 68

__global__ void __launch_bounds__(256, 2)
ctx_out_kernel(const float* __restrict__ att, const unsigned* __restrict__ Vt,
               const unsigned* __restrict__ WhT, const float* __restrict__ bh,
               float* __restrict__ out)
{
    extern __shared__ unsigned cs[];
    unsigned* As = cs;                 // [128][68]
    unsigned* Bs = cs + 128 * CTS;     // [128][68]

    const int b   = blockIdx.y;
    const int q0  = blockIdx.x * 128;
    const int tid = threadIdx.x;
    const int w   = tid >> 5;
    const int tx  = tid & 31;
    const int lane4 = tx & 3;
    const int wq    = tx >> 2;
    const int mb = (w & 3) * 32;

    const int nb1 = (w >> 2) * 32;
    float ctx_acc[2][4][4];
    #pragma unroll
    for (int m = 0; m < 2; m++)
        #pragma unroll
        for (int n = 0; n < 4; n++)
            #pragma unroll
            for (int c = 0; c < 4; c++) ctx_acc[m][n][c] = 0.f;

    for (int kc = 0; kc < 8; kc++) {
        __syncthreads();
        #pragma unroll
        for (int it = 0; it < 8; it++) {
            int idx = it * 256 + tid;
            int q   = idx >> 4;
            int c4  = (idx & 15) * 4;
            float4 v = *reinterpret_cast<const float4*>(
                &att[((size_t)(b * SEQ) + q0 + q) * SEQ + kc * 64 + c4]);
            *reinterpret_cast<uint4*>(&As[q * CTS + c4]) =
                make_uint4(f2tf32(v.x), f2tf32(v.y), f2tf32(v.z), f2tf32(v.w));
        }
        #pragma unroll
        for (int it = 0; it < 4; it++) {
            int idx = it * 256 + tid;
            int d   = idx >> 4;
            int c4  = (idx & 15) * 4;
            uint4 v = *reinterpret_cast<const uint4*>(
                &Vt[((size_t)b * HDIM + d) * SEQ + kc * 64 + c4]);
            *reinterpret_cast<uint4*>(&Bs[d * CTS + c4]) = v;
        }
        __syncthreads();

        #pragma unroll
        for (int kk = 0; kk < 8; kk++) {
            unsigned a[2][4], bf[4][2];
            #pragma unroll
            for (int m = 0; m < 2; m++) {
                int row = mb + m * 16 + wq;
                int col = kk * 8 + lane4;
                a[m][0] = As[row * CTS + col];
                a[m][1] = As[(row + 8) * CTS + col];
                a[m][2] = As[row * CTS + col + 4];
                a[m][3] = As[(row + 8) * CTS + col + 4];
            }
            #pragma unroll
            for (int n = 0; n < 4; n++) {
                int nr = nb1 + n * 8 + wq;
                bf[n][0] = Bs[nr * CTS + kk * 8 + lane4];
                bf[n][1] = Bs[nr * CTS + kk * 8 + lane4 + 4];
            }
            #pragma unroll
            for (int m = 0; m < 2; m++)
                #pragma unroll
                for (int n = 0; n < 4; n++) {
                    float* d = ctx_acc[m][n];
                    asm volatile(
                        "mma.sync.aligned.m16n8k8.row.col.f32.tf32.tf32.f32 "
                        "{%0,%1,%2,%3}, {%4,%5,%6,%7}, {%8,%9}, {%0,%1,%2,%3};\n"
                        : "+f"(d[0]), "+f"(d[1]), "+f"(d[2]), "+f"(d[3])
                        : "r"(a[m][0]), "r"(a[m][1]), "r"(a[m][2]), "r"(a[m][3]),
                          "r"(bf[n][0]), "r"(bf[n][1]));
                }
        }
    }

    __syncthreads();
    #pragma unroll
    for (int m = 0; m < 2; m++) {
        int row = mb + m * 16 + wq;
        #pragma unroll
        for (int n = 0; n < 4; n++) {
            int col = nb1 + n * 8 + lane4 * 2;
            As[row * CTS + col]           = f2tf32(ctx_acc[m][n][0]);
            As[row * CTS + col + 1]       = f2tf32(ctx_acc[m][n][1]);
            As[(row + 8) * CTS + col]     = f2tf32(ctx_acc[m][n][2]);
            As[(row + 8) * CTS + col + 1] = f2tf32(ctx_acc[m][n][3]);
        }
    }

    const int nb2 = (w >> 2) * 64;
    for (int p = 0; p < 2; p++) {
        __syncthreads();
        #pragma unroll
        for (int it = 0; it < 8; it++) {
            int idx = it * 256 + tid;
            int r   = idx >> 4;
            int c4  = (idx & 15) * 4;
            uint4 v = *reinterpret_cast<const uint4*>(
                &WhT[(size_t)(p * 128 + r) * HDIM + c4]);
            *reinterpret_cast<uint4*>(&Bs[r * CTS + c4]) = v;
        }
        __syncthreads();

        float acc[2][8][4];
        #pragma unroll
        for (int m = 0; m < 2; m++)
            #pragma unroll
            for (int n = 0; n < 8; n++)
                #pragma unroll
                for (int c = 0; c < 4; c++) acc[m][n][c] = 0.f;

        #pragma unroll
        for (int kk = 0; kk < 8; kk++) {
            unsigned a[2][4], bf[8][2];
            #pragma unroll
            for (int m = 0; m < 2; m++) {
                int row = mb + m * 16 + wq;
                int col = kk * 8 + lane4;
                a[m][0] = As[row * CTS + col];
                a[m][1] = As[(row + 8) * CTS + col];
                a[m][2] = As[row * CTS + col + 4];
                a[m][3] = As[(row + 8) * CTS + col + 4];
            }
            #pragma unroll
            for (int n = 0; n < 8; n++) {
                int nr = nb2 + n * 8 + wq;
                bf[n][0] = Bs[nr * CTS + kk * 8 + lane4];
                bf[n][1] = Bs[nr * CTS + kk * 8 + lane4 + 4];
            }
            #pragma unroll
            for (int m = 0; m < 2; m++)
                #pragma unroll
                for (int n = 0; n < 8; n++) {
                    float* d = acc[m][n];
                    asm volatile(
                        "mma.sync.aligned.m16n8k8.row.col.f32.tf32.tf32.f32 "
                        "{%0,%1,%2,%3}, {%4,%5,%6,%7}, {%8,%9}, {%0,%1,%2,%3};\n"
                        : "+f"(d[0]), "+f"(d[1]), "+f"(d[2]), "+f"(d[3])
                        : "r"(a[m][0]), "r"(a[m][1]), "r"(a[m][2]), "r"(a[m][3]),
                          "r"(bf[n][0]), "r"(bf[n][1]));
                }
        }

        #pragma unroll
        for (int m = 0; m < 2; m++) {
            int row = q0 + mb + m * 16 + wq;
            #pragma unroll
            for (int n = 0; n < 8; n++) {
                int col = p * 128 + nb2 + n * 8 + lane4 * 2;
                float2 bb = *reinterpret_cast<const float2*>(&bh[col]);
                *reinterpret_cast<float2*>(
                    &out[((size_t)(b * SEQ) + row) * HID + col]) =
                    make_float2(acc[m][n][0] + bb.x, acc[m][n][1] + bb.y);
                *reinterpret_cast<float2*>(
                    &out[((size_t)(b * SEQ) + row + 8) * HID + col]) =
                    make_float2(acc[m][n][2] + bb.x, acc[m][n][3] + bb.y);
            }
        }
    }
}

// ---------------------------------------------------------------------------
extern "C" void kernel_launch(void* const* d_in, const int* in_sizes, int n_in,
                              void* d_out, int out_size)
{
    const float* query = (const float*)d_in[0];
    const float* key   = (const float*)d_in[1];
    const float* value = (const float*)d_in[2];
    const int*   mask  = (const int*)  d_in[3];
    const float* Wq    = (const float*)d_in[4];
    const float* bq    = (const float*)d_in[5];
    const float* Wk    = (const float*)d_in[6];
    const float* bk    = (const float*)d_in[7];
    const float* Wv    = (const float*)d_in[8];
    const float* bv    = (const float*)d_in[9];
    const float* Wh    = (const float*)d_in[10];
    const float* bh    = (const float*)d_in[11];

    float* out     = (float*)d_out;                          // [B,S,HID]
    float* att_out = (float*)d_out + (size_t)MROWS * HID;    // [B,S,S]

    unsigned *pQt, *pKt, *pWt, *pVt, *pWhT;
    cudaGetSymbolAddress((void**)&pQt, g_Qt);
    cudaGetSymbolAddress((void**)&pKt, g_Kt);
    cudaGetSymbolAddress((void**)&pWt, g_Wt);
    cudaGetSymbolAddress((void**)&pVt, g_Vt);
    cudaGetSymbolAddress((void**)&pWhT, g_WhT);
    unsigned* pWtq = pWt;
    unsigned* pWtk = pWt + HID * HID;
    unsigned* pWtv = pWt + 2 * HID * HID;

    // All weight transposes in one launch
    transpose_all_kernel<<<160, 256>>>(Wq, Wk, Wv, Wh, pWtq, pWtk, pWtv, pWhT);

    // All three projections in ONE launch
    size_t gsmem = (size_t)(2 * 128 * GS + 2 * 64 * GS) * sizeof(unsigned); // 55296
    cudaFuncSetAttribute(gemm_fused_kernel,
                         cudaFuncAttributeMaxDynamicSharedMemorySize, (int)gsmem);
    gemm_fused_kernel<<<dim3(9, MROWS / 128), 256, gsmem>>>(
        query, key, value, pWtq, pWtk, pWtv, bq, bk, bv, pQt, pKt, pVt);

    // Attention (16-row q-tile, 2 CTAs/SM)
    size_t smem = (size_t)(16 * QS_ST + 2 * 128 * KS_ST) * sizeof(unsigned)
                  + 16 * 9 * sizeof(float);   // 86848 B
    cudaFuncSetAttribute(attn_kernel,
                         cudaFuncAttributeMaxDynamicSharedMemorySize, (int)smem);
    attn_kernel<<<dim3(SEQ / 16, BATCH), 256, smem>>>(pQt, pKt, mask, att_out);

    // ctx + output projection
    size_t csmem = (size_t)(2 * 128 * CTS) * sizeof(unsigned);   // 69632 B
    cudaFuncSetAttribute(ctx_out_kernel,
                         cudaFuncAttributeMaxDynamicSharedMemorySize, (int)csmem);
    ctx_out_kernel<<<dim3(SEQ / 128, BATCH), 256, csmem>>>(
        att_out, pVt, pWhT, bh, out);
}

// round 16
// speedup vs baseline: 1.4075x; 1.4075x over previous
#include <cuda_runtime.h>
#include <cuda_bf16.h>
#include <math.h>

// Problem constants
#define BATCH   64
#define SEQ     512
#define HID     256
#define NHEADS  4
#define HDIM    64
#define MROWS   (BATCH*SEQ)      // 32768
#define C_EXP   0.18033688011112042f   // 0.125 * log2(e)

// Scratch (alloc-free rule: __device__ globals)
__device__ unsigned g_Qt[(size_t)MROWS * HID];                // Q proj tf32, row-major
__device__ unsigned g_Kt[(size_t)MROWS * HID];                // K proj tf32, [B][H][S][64]
__device__ unsigned g_Vt[(size_t)BATCH * HDIM * SEQ];         // V^T per batch, tf32
__device__ unsigned g_Wt[2 * HID * HID + HID * HDIM];         // Wq^T, Wk^T, Wv^T tf32
__device__ unsigned g_WhT[HID * HDIM];                        // Wh^T tf32 [256][64]

__device__ __forceinline__ unsigned f2tf32(float x)
{
    unsigned o;
    asm("cvt.rna.tf32.f32 %0, %1;" : "=r"(o) : "f"(x));
    return o;
}

__device__ __forceinline__ void cp16(void* dst_smem, const void* src_gmem)
{
    unsigned s = (unsigned)__cvta_generic_to_shared(dst_smem);
    asm volatile("cp.async.cg.shared.global [%0], [%1], 16;" :: "r"(s), "l"(src_gmem));
}
__device__ __forceinline__ void cp_commit()
{
    asm volatile("cp.async.commit_group;");
}
__device__ __forceinline__ void cp_wait0()
{
    asm volatile("cp.async.wait_group 0;");
}

// ---------------------------------------------------------------------------
// All four weight transposes in ONE kernel. 160 blocks of 32x32 tiles.
// ---------------------------------------------------------------------------
__global__ void __launch_bounds__(256)
transpose_all_kernel(const float* __restrict__ Wq, const float* __restrict__ Wk,
                     const float* __restrict__ Wv, const float* __restrict__ Wh,
                     unsigned* __restrict__ dq, unsigned* __restrict__ dk,
                     unsigned* __restrict__ dv, unsigned* __restrict__ dh)
{
    __shared__ unsigned t[32][33];
    int id = blockIdx.x;
    const float* src; unsigned* dst; int K, N, lid;
    if (id < 64)       { src = Wq; dst = dq; K = 256; N = 256; lid = id; }
    else if (id < 128) { src = Wk; dst = dk; K = 256; N = 256; lid = id - 64; }
    else if (id < 144) { src = Wv; dst = dv; K = 256; N = 64;  lid = id - 128; }
    else               { src = Wh; dst = dh; K = 64;  N = 256; lid = id - 144; }
    int kt = K / 32;
    int k0 = (lid % kt) * 32;
    int n0 = (lid / kt) * 32;
    const int tx = threadIdx.x & 31;
    const int ty = threadIdx.x >> 5;

    #pragma unroll
    for (int i = 0; i < 4; i++) {
        int r = ty + i * 8;
        t[tx][r] = f2tf32(src[(size_t)(k0 + r) * N + n0 + tx]);
    }
    __syncthreads();
    #pragma unroll
    for (int i = 0; i < 4; i++) {
        int r = ty + i * 8;
        dst[(size_t)(n0 + r) * K + k0 + tx] = t[r][tx];
    }
}

// ---------------------------------------------------------------------------
// FUSED projection GEMMs: one launch covers Q, K, V.
// grid.x = 9: 0..3 -> Q n-tiles, 4..7 -> K n-tiles, 8 -> V.
// A staged via cp.async as RAW fp32 bits (tf32 mma truncates to E8M10);
// W staged via cp.async (pre-converted tf32). No in-loop cvt at all.
// tout=1: Vt[b][n][s]; tout=2: flat [M][256] (Qt); tout=3: Kt[b][h][s][d].
// ---------------------------------------------------------------------------
#define GS 36

__global__ void __launch_bounds__(256, 2)
gemm_fused_kernel(const float* __restrict__ Aq, const float* __restrict__ Ak,
                  const float* __restrict__ Av,
                  const unsigned* __restrict__ Wtq, const unsigned* __restrict__ Wtk,
                  const unsigned* __restrict__ Wtv,
                  const float* __restrict__ bq, const float* __restrict__ bk,
                  const float* __restrict__ bv,
                  unsigned* __restrict__ Qt, unsigned* __restrict__ Kt,
                  unsigned* __restrict__ Vt)
{
    extern __shared__ unsigned gsm[];
    unsigned* Asb[2] = { gsm, gsm + 128 * GS };
    unsigned* Wsb[2] = { gsm + 2 * 128 * GS, gsm + 2 * 128 * GS + 64 * GS };

    const int bx = blockIdx.x;
    const float* A; const unsigned* Wt; const float* bias; unsigned* Ct;
    int tout, n0;
    if (bx < 4)      { A = Aq; Wt = Wtq; bias = bq; Ct = Qt; tout = 2; n0 = bx * 64; }
    else if (bx < 8) { A = Ak; Wt = Wtk; bias = bk; Ct = Kt; tout = 3; n0 = (bx - 4) * 64; }
    else             { A = Av; Wt = Wtv; bias = bv; Ct = Vt; tout = 1; n0 = 0; }

    const int m0  = blockIdx.y * 128;
    const int tid = threadIdx.x;
    const int w   = tid >> 5;
    const int tx  = tid & 31;
    const int lane4 = tx & 3;
    const int wq    = tx >> 2;
    const int mb = (w & 3) * 32;
    const int nb = (w >> 2) * 32;

    const int lr  = tid >> 3;          // stage row (0..31)
    const int lc4 = (tid & 7) * 4;     // col group *4

    #define CPA(kc, buf) do { \
        _Pragma("unroll") \
        for (int it = 0; it < 4; it++) \
            cp16(&Asb[buf][(lr + it * 32) * GS + lc4], \
                 &A[(size_t)(m0 + lr + it * 32) * 256 + (kc) * 32 + lc4]); \
    } while (0)
    #define CPW(kc, buf) do { \
        _Pragma("unroll") \
        for (int it = 0; it < 2; it++) \
            cp16(&Wsb[buf][(lr + it * 32) * GS + lc4], \
                 &Wt[(size_t)(n0 + lr + it * 32) * 256 + (kc) * 32 + lc4]); \
    } while (0)

    float acc[2][4][4];
    #pragma unroll
    for (int m = 0; m < 2; m++)
        #pragma unroll
        for (int n = 0; n < 4; n++)
            #pragma unroll
            for (int c = 0; c < 4; c++) acc[m][n][c] = 0.f;

    // prologue: chunk 0 in flight
    CPA(0, 0);
    CPW(0, 0);
    cp_commit();
    cp_wait0();
    __syncthreads();

    #pragma unroll 2
    for (int kc8 = 0; kc8 < 8; kc8++) {
        int cur = kc8 & 1;
        if (kc8 < 7) {
            CPA(kc8 + 1, 1 - cur);
            CPW(kc8 + 1, 1 - cur);
            cp_commit();
        }

        unsigned* As = Asb[cur];
        unsigned* Ws = Wsb[cur];
        #pragma unroll
        for (int kk = 0; kk < 4; kk++) {
            unsigned a[2][4], bf[4][2];
            #pragma unroll
            for (int m = 0; m < 2; m++) {
                int row = mb + m * 16 + wq;
                int col = kk * 8 + lane4;
                a[m][0] = As[row * GS + col];
                a[m][1] = As[(row + 8) * GS + col];
                a[m][2] = As[row * GS + col + 4];
                a[m][3] = As[(row + 8) * GS + col + 4];
            }
            #pragma unroll
            for (int n = 0; n < 4; n++) {
                int nr = nb + n * 8 + wq;
                bf[n][0] = Ws[nr * GS + kk * 8 + lane4];
                bf[n][1] = Ws[nr * GS + kk * 8 + lane4 + 4];
            }
            #pragma unroll
            for (int m = 0; m < 2; m++)
                #pragma unroll
                for (int n = 0; n < 4; n++) {
                    float* d = acc[m][n];
                    asm volatile(
                        "mma.sync.aligned.m16n8k8.row.col.f32.tf32.tf32.f32 "
                        "{%0,%1,%2,%3}, {%4,%5,%6,%7}, {%8,%9}, {%0,%1,%2,%3};\n"
                        : "+f"(d[0]), "+f"(d[1]), "+f"(d[2]), "+f"(d[3])
                        : "r"(a[m][0]), "r"(a[m][1]), "r"(a[m][2]), "r"(a[m][3]),
                          "r"(bf[n][0]), "r"(bf[n][1]));
                }
        }

        if (kc8 < 7) {
            cp_wait0();
            __syncthreads();
        }
    }
    #undef CPA
    #undef CPW

    if (tout == 2) {
        #pragma unroll
        for (int m = 0; m < 2; m++) {
            int row = m0 + mb + m * 16 + wq;
            #pragma unroll
            for (int n = 0; n < 4; n++) {
                int col = n0 + nb + n * 8 + lane4 * 2;
                float2 bb = *reinterpret_cast<const float2*>(&bias[col]);
                Ct[(size_t)row * HID + col]           = f2tf32(acc[m][n][0] + bb.x);
                Ct[(size_t)row * HID + col + 1]       = f2tf32(acc[m][n][1] + bb.y);
                Ct[(size_t)(row + 8) * HID + col]     = f2tf32(acc[m][n][2] + bb.x);
                Ct[(size_t)(row + 8) * HID + col + 1] = f2tf32(acc[m][n][3] + bb.y);
            }
        }
    } else if (tout == 3) {
        #pragma unroll
        for (int m = 0; m < 2; m++) {
            int r0 = m0 + mb + m * 16 + wq;
            int r1 = r0 + 8;
            int bb0 = r0 >> 9, s0 = r0 & 511, s1 = r1 & 511;
            #pragma unroll
            for (int n = 0; n < 4; n++) {
                int col = n0 + nb + n * 8 + lane4 * 2;
                int h = col >> 6, d = col & 63;
                size_t base = ((size_t)bb0 * NHEADS + h) * SEQ;
                float2 bb = *reinterpret_cast<const float2*>(&bias[col]);
                Ct[(base + s0) * HDIM + d]     = f2tf32(acc[m][n][0] + bb.x);
                Ct[(base + s0) * HDIM + d + 1] = f2tf32(acc[m][n][1] + bb.y);
                Ct[(base + s1) * HDIM + d]     = f2tf32(acc[m][n][2] + bb.x);
                Ct[(base + s1) * HDIM + d + 1] = f2tf32(acc[m][n][3] + bb.y);
            }
        }
    } else {
        #pragma unroll
        for (int m = 0; m < 2; m++) {
            int r0 = m0 + mb + m * 16 + wq;
            int r1 = r0 + 8;
            int b0 = r0 >> 9, s0 = r0 & 511;
            int s1 = r1 & 511;
            #pragma unroll
            for (int n = 0; n < 4; n++) {
                int col = n0 + nb + n * 8 + lane4 * 2;
                float2 bb = *reinterpret_cast<const float2*>(&bias[col]);
                Ct[((size_t)b0 * HDIM + col) * SEQ + s0]     = f2tf32(acc[m][n][0] + bb.x);
                Ct[((size_t)b0 * HDIM + col + 1) * SEQ + s0] = f2tf32(acc[m][n][1] + bb.y);
                Ct[((size_t)b0 * HDIM + col) * SEQ + s1]     = f2tf32(acc[m][n][2] + bb.x);
                Ct[((size_t)b0 * HDIM + col + 1) * SEQ + s1] = f2tf32(acc[m][n][3] + bb.y);
            }
        }
    }
}

// ---------------------------------------------------------------------------
// Slim exp2: no clamp (inputs bounded), 2-op exponent reconstruction.
// ---------------------------------------------------------------------------
__device__ __forceinline__ float exp2s(float y)
{
    float t = y + 12582912.0f;
    float f = y - (t - 12582912.0f);
    float p = 0.0013333558f;
    p = fmaf(p, f, 0.0096181291f);
    p = fmaf(p, f, 0.0555041087f);
    p = fmaf(p, f, 0.2402265069f);
    p = fmaf(p, f, 0.6931471806f);
    p = fmaf(p, f, 1.0f);
    unsigned r = (__float_as_uint(t) << 23) + 0x3F800000u;
    return __uint_as_float(r) * p;
}

// ---------------------------------------------------------------------------
// Attention kernel (round-8/12 proven version, FROZEN).
// ---------------------------------------------------------------------------
#define QS_ST 260
#define KS_ST 68

__global__ void __launch_bounds__(256)
attn_kernel(const unsigned* __restrict__ Qt, const unsigned* __restrict__ Kt,
            const int* __restrict__ mask, float* __restrict__ att_out)
{
    extern __shared__ unsigned smu[];
    unsigned* Qs = smu;                              // [32][260]
    unsigned* Ksb[2] = { smu + 32 * QS_ST,
                         smu + 32 * QS_ST + 256 * KS_ST };   // 2 x [256][68]
    float* red = (float*)(smu + 32 * QS_ST + 2 * 256 * KS_ST);  // [32][9]

    const int b   = blockIdx.y;
    const int q0  = blockIdx.x * 32;
    const int tid = threadIdx.x;
    const int w   = tid >> 5;
    const int tx  = tid & 31;
    const int lane4 = tx & 3;
    const int wq    = tx >> 2;

    {
        const unsigned* src = &Kt[(((size_t)b * NHEADS + 0) * SEQ + 0) * HDIM];
        #pragma unroll
        for (int it = 0; it < 16; it++) {
            int idx = it * 256 + tid;
            int row = idx >> 4;
            int c4  = (idx & 15) * 4;
            cp16(&Ksb[0][row * KS_ST + c4], &src[row * HDIM + c4]);
        }
        cp_commit();
    }

    #pragma unroll
    for (int it = 0; it < 8; it++) {
        int idx = it * 256 + tid;
        int q   = idx >> 6;
        int c4  = (idx & 63) * 4;
        uint4 v = *reinterpret_cast<const uint4*>(
            &Qt[(size_t)(b * SEQ + q0 + q) * HID + c4]);
        *reinterpret_cast<uint4*>(&Qs[q * QS_ST + c4]) = v;
    }

    unsigned long long mbits = 0ull;
    #pragma unroll
    for (int rs = 0; rs < 4; rs++) {
        int row = (rs >> 1) * 16 + (rs & 1) * 8 + wq;
        const int* mrow = mask + ((size_t)b * SEQ + q0 + row) * SEQ;
        #pragma unroll
        for (int nt = 0; nt < 8; nt++) {
            int2 mv = *reinterpret_cast<const int2*>(&mrow[nt * 64 + w * 8 + lane4 * 2]);
            int bi = rs * 16 + nt * 2;
            mbits |= ((unsigned long long)(mv.x != 0)) << bi;
            mbits |= ((unsigned long long)(mv.y != 0)) << (bi + 1);
        }
    }

    float att_acc[64];
    #pragma unroll
    for (int i = 0; i < 64; i++) att_acc[i] = 0.f;

    cp_wait0();
    __syncthreads();

    float acc[64];

    #pragma unroll 1
    for (int h = 0; h < NHEADS; h++) {
        {
            const unsigned* src = &Kt[(((size_t)b * NHEADS + h) * SEQ + 256) * HDIM];
            #pragma unroll
            for (int it = 0; it < 16; it++) {
                int idx = it * 256 + tid;
                int row = idx >> 4;
                int c4  = (idx & 15) * 4;
                cp16(&Ksb[1][row * KS_ST + c4], &src[row * HDIM + c4]);
            }
            cp_commit();
        }
        #pragma unroll
        for (int i = 0; i < 64; i++) acc[i] = 0.f;

        #pragma unroll
        for (int ks = 0; ks < 8; ks++) {
            unsigned a[2][4];
            #pragma unroll
            for (int m = 0; m < 2; m++) {
                int row = m * 16 + wq;
                int cb  = h * 64 + ks * 8 + lane4;
                a[m][0] = Qs[row * QS_ST + cb];
                a[m][1] = Qs[(row + 8) * QS_ST + cb];
                a[m][2] = Qs[row * QS_ST + cb + 4];
                a[m][3] = Qs[(row + 8) * QS_ST + cb + 4];
            }
            #pragma unroll
            for (int ntl = 0; ntl < 4; ntl++) {
                int krow = ntl * 64 + w * 8 + wq;
                unsigned b0 = Ksb[0][krow * KS_ST + ks * 8 + lane4];
                unsigned b1 = Ksb[0][krow * KS_ST + ks * 8 + lane4 + 4];
                #pragma unroll
                for (int m = 0; m < 2; m++) {
                    float* d = &acc[(m * 8 + ntl) * 4];
                    asm volatile(
                        "mma.sync.aligned.m16n8k8.row.col.f32.tf32.tf32.f32 "
                        "{%0,%1,%2,%3}, {%4,%5,%6,%7}, {%8,%9}, {%0,%1,%2,%3};\n"
                        : "+f"(d[0]), "+f"(d[1]), "+f"(d[2]), "+f"(d[3])
                        : "r"(a[m][0]), "r"(a[m][1]), "r"(a[m][2]), "r"(a[m][3]),
                          "r"(b0), "r"(b1));
                }
            }
        }
        cp_wait0();
        __syncthreads();

        if (h < NHEADS - 1) {
            const unsigned* src = &Kt[(((size_t)b * NHEADS + h + 1) * SEQ) * HDIM];
            #pragma unroll
            for (int it = 0; it < 16; it++) {
                int idx = it * 256 + tid;
                int row = idx >> 4;
                int c4  = (idx & 15) * 4;
                cp16(&Ksb[0][row * KS_ST + c4], &src[row * HDIM + c4]);
            }
            cp_commit();
        }

        #pragma unroll
        for (int ks = 0; ks < 8; ks++) {
            unsigned a[2][4];
            #pragma unroll
            for (int m = 0; m < 2; m++) {
                int row = m * 16 + wq;
                int cb  = h * 64 + ks * 8 + lane4;
                a[m][0] = Qs[row * QS_ST + cb];
                a[m][1] = Qs[(row + 8) * QS_ST + cb];
                a[m][2] = Qs[row * QS_ST + cb + 4];
                a[m][3] = Qs[(row + 8) * QS_ST + cb + 4];
            }
            #pragma unroll
            for (int ntl = 0; ntl < 4; ntl++) {
                int krow = ntl * 64 + w * 8 + wq;
                unsigned b0 = Ksb[1][krow * KS_ST + ks * 8 + lane4];
                unsigned b1 = Ksb[1][krow * KS_ST + ks * 8 + lane4 + 4];
                #pragma unroll
                for (int m = 0; m < 2; m++) {
                    float* d = &acc[(m * 8 + 4 + ntl) * 4];
                    asm volatile(
                        "mma.sync.aligned.m16n8k8.row.col.f32.tf32.tf32.f32 "
                        "{%0,%1,%2,%3}, {%4,%5,%6,%7}, {%8,%9}, {%0,%1,%2,%3};\n"
                        : "+f"(d[0]), "+f"(d[1]), "+f"(d[2]), "+f"(d[3])
                        : "r"(a[m][0]), "r"(a[m][1]), "r"(a[m][2]), "r"(a[m][3]),
                          "r"(b0), "r"(b1));
                }
            }
        }

        float rsum[4];
        #pragma unroll
        for (int rs = 0; rs < 4; rs++) {
            int m = rs >> 1, cb2 = (rs & 1) * 2;
            float s = 0.f;
            #pragma unroll
            for (int nt = 0; nt < 8; nt++)
                #pragma unroll
                for (int p = 0; p < 2; p++) {
                    int id = (m * 8 + nt) * 4 + cb2 + p;
                    int bi = rs * 16 + nt * 2 + p;
                    float e = exp2s(acc[id] * C_EXP);
                    e = ((mbits >> bi) & 1ull) ? e : 0.f;
                    acc[id] = e;
                    s += e;
                }
            s += __shfl_xor_sync(0xffffffffu, s, 1);
            s += __shfl_xor_sync(0xffffffffu, s, 2);
            rsum[rs] = s;
        }
        if (lane4 == 0) {
            #pragma unroll
            for (int rs = 0; rs < 4; rs++) {
                int row = (rs >> 1) * 16 + (rs & 1) * 8 + wq;
                red[row * 9 + w] = rsum[rs];
            }
        }
        __syncthreads();
        #pragma unroll
        for (int rs = 0; rs < 4; rs++) {
            int row = (rs >> 1) * 16 + (rs & 1) * 8 + wq;
            float s = 0.f;
            #pragma unroll
            for (int ww = 0; ww < 8; ww++) s += red[row * 9 + ww];
            float inv = 0.25f / s;
            int m = rs >> 1, cb2 = (rs & 1) * 2;
            #pragma unroll
            for (int nt = 0; nt < 8; nt++)
                #pragma unroll
                for (int p = 0; p < 2; p++) {
                    int id = (m * 8 + nt) * 4 + cb2 + p;
                    att_acc[id] += acc[id] * inv;
                }
        }
        if (h < NHEADS - 1) {
            cp_wait0();
            __syncthreads();
        }
    }

    #pragma unroll
    for (int rs = 0; rs < 4; rs++) {
        int row = (rs >> 1) * 16 + (rs & 1) * 8 + wq;
        int m = rs >> 1, cb2 = (rs & 1) * 2;
        float* dst = att_out + ((size_t)b * SEQ + q0 + row) * SEQ;
        #pragma unroll
        for (int nt = 0; nt < 8; nt++) {
            int col = nt * 64 + w * 8 + lane4 * 2;
            *reinterpret_cast<float2*>(&dst[col]) =
                make_float2(att_acc[(m * 8 + nt) * 4 + cb2],
                            att_acc[(m * 8 + nt) * 4 + cb2 + 1]);
        }
    }
}

// ---------------------------------------------------------------------------
// ctx + out-proj, tf32 tensor cores (round-12 proven version, 2 CTAs/SM).
// ---------------------------------------------------------------------------
#define CTS 68

__global__ void __launch_bounds__(256, 2)
ctx_out_kernel(const float* __restrict__ att, const unsigned* __restrict__ Vt,
               const unsigned* __restrict__ WhT, const float* __restrict__ bh,
               float* __restrict__ out)
{
    extern __shared__ unsigned cs[];
    unsigned* As = cs;                 // [128][68]
    unsigned* Bs = cs + 128 * CTS;     // [128][68]

    const int b   = blockIdx.y;
    const int q0  = blockIdx.x * 128;
    const int tid = threadIdx.x;
    const int w   = tid >> 5;
    const int tx  = tid & 31;
    const int lane4 = tx & 3;
    const int wq    = tx >> 2;
    const int mb = (w & 3) * 32;

    const int nb1 = (w >> 2) * 32;
    float ctx_acc[2][4][4];
    #pragma unroll
    for (int m = 0; m < 2; m++)
        #pragma unroll
        for (int n = 0; n < 4; n++)
            #pragma unroll
            for (int c = 0; c < 4; c++) ctx_acc[m][n][c] = 0.f;

    for (int kc = 0; kc < 8; kc++) {
        __syncthreads();
        #pragma unroll
        for (int it = 0; it < 8; it++) {
            int idx = it * 256 + tid;
            int q   = idx >> 4;
            int c4  = (idx & 15) * 4;
            float4 v = *reinterpret_cast<const float4*>(
                &att[((size_t)(b * SEQ) + q0 + q) * SEQ + kc * 64 + c4]);
            *reinterpret_cast<uint4*>(&As[q * CTS + c4]) =
                make_uint4(f2tf32(v.x), f2tf32(v.y), f2tf32(v.z), f2tf32(v.w));
        }
        #pragma unroll
        for (int it = 0; it < 4; it++) {
            int idx = it * 256 + tid;
            int d   = idx >> 4;
            int c4  = (idx & 15) * 4;
            uint4 v = *reinterpret_cast<const uint4*>(
                &Vt[((size_t)b * HDIM + d) * SEQ + kc * 64 + c4]);
            *reinterpret_cast<uint4*>(&Bs[d * CTS + c4]) = v;
        }
        __syncthreads();

        #pragma unroll
        for (int kk = 0; kk < 8; kk++) {
            unsigned a[2][4], bf[4][2];
            #pragma unroll
            for (int m = 0; m < 2; m++) {
                int row = mb + m * 16 + wq;
                int col = kk * 8 + lane4;
                a[m][0] = As[row * CTS + col];
                a[m][1] = As[(row + 8) * CTS + col];
                a[m][2] = As[row * CTS + col + 4];
                a[m][3] = As[(row + 8) * CTS + col + 4];
            }
            #pragma unroll
            for (int n = 0; n < 4; n++) {
                int nr = nb1 + n * 8 + wq;
                bf[n][0] = Bs[nr * CTS + kk * 8 + lane4];
                bf[n][1] = Bs[nr * CTS + kk * 8 + lane4 + 4];
            }
            #pragma unroll
            for (int m = 0; m < 2; m++)
                #pragma unroll
                for (int n = 0; n < 4; n++) {
                    float* d = ctx_acc[m][n];
                    asm volatile(
                        "mma.sync.aligned.m16n8k8.row.col.f32.tf32.tf32.f32 "
                        "{%0,%1,%2,%3}, {%4,%5,%6,%7}, {%8,%9}, {%0,%1,%2,%3};\n"
                        : "+f"(d[0]), "+f"(d[1]), "+f"(d[2]), "+f"(d[3])
                        : "r"(a[m][0]), "r"(a[m][1]), "r"(a[m][2]), "r"(a[m][3]),
                          "r"(bf[n][0]), "r"(bf[n][1]));
                }
        }
    }

    __syncthreads();
    #pragma unroll
    for (int m = 0; m < 2; m++) {
        int row = mb + m * 16 + wq;
        #pragma unroll
        for (int n = 0; n < 4; n++) {
            int col = nb1 + n * 8 + lane4 * 2;
            As[row * CTS + col]           = f2tf32(ctx_acc[m][n][0]);
            As[row * CTS + col + 1]       = f2tf32(ctx_acc[m][n][1]);
            As[(row + 8) * CTS + col]     = f2tf32(ctx_acc[m][n][2]);
            As[(row + 8) * CTS + col + 1] = f2tf32(ctx_acc[m][n][3]);
        }
    }

    const int nb2 = (w >> 2) * 64;
    for (int p = 0; p < 2; p++) {
        __syncthreads();
        #pragma unroll
        for (int it = 0; it < 8; it++) {
            int idx = it * 256 + tid;
            int r   = idx >> 4;
            int c4  = (idx & 15) * 4;
            uint4 v = *reinterpret_cast<const uint4*>(
                &WhT[(size_t)(p * 128 + r) * HDIM + c4]);
            *reinterpret_cast<uint4*>(&Bs[r * CTS + c4]) = v;
        }
        __syncthreads();

        float acc[2][8][4];
        #pragma unroll
        for (int m = 0; m < 2; m++)
            #pragma unroll
            for (int n = 0; n < 8; n++)
                #pragma unroll
                for (int c = 0; c < 4; c++) acc[m][n][c] = 0.f;

        #pragma unroll
        for (int kk = 0; kk < 8; kk++) {
            unsigned a[2][4], bf[8][2];
            #pragma unroll
            for (int m = 0; m < 2; m++) {
                int row = mb + m * 16 + wq;
                int col = kk * 8 + lane4;
                a[m][0] = As[row * CTS + col];
                a[m][1] = As[(row + 8) * CTS + col];
                a[m][2] = As[row * CTS + col + 4];
                a[m][3] = As[(row + 8) * CTS + col + 4];
            }
            #pragma unroll
            for (int n = 0; n < 8; n++) {
                int nr = nb2 + n * 8 + wq;
                bf[n][0] = Bs[nr * CTS + kk * 8 + lane4];
                bf[n][1] = Bs[nr * CTS + kk * 8 + lane4 + 4];
            }
            #pragma unroll
            for (int m = 0; m < 2; m++)
                #pragma unroll
                for (int n = 0; n < 8; n++) {
                    float* d = acc[m][n];
                    asm volatile(
                        "mma.sync.aligned.m16n8k8.row.col.f32.tf32.tf32.f32 "
                        "{%0,%1,%2,%3}, {%4,%5,%6,%7}, {%8,%9}, {%0,%1,%2,%3};\n"
                        : "+f"(d[0]), "+f"(d[1]), "+f"(d[2]), "+f"(d[3])
                        : "r"(a[m][0]), "r"(a[m][1]), "r"(a[m][2]), "r"(a[m][3]),
                          "r"(bf[n][0]), "r"(bf[n][1]));
                }
        }

        #pragma unroll
        for (int m = 0; m < 2; m++) {
            int row = q0 + mb + m * 16 + wq;
            #pragma unroll
            for (int n = 0; n < 8; n++) {
                int col = p * 128 + nb2 + n * 8 + lane4 * 2;
                float2 bb = *reinterpret_cast<const float2*>(&bh[col]);
                *reinterpret_cast<float2*>(
                    &out[((size_t)(b * SEQ) + row) * HID + col]) =
                    make_float2(acc[m][n][0] + bb.x, acc[m][n][1] + bb.y);
                *reinterpret_cast<float2*>(
                    &out[((size_t)(b * SEQ) + row + 8) * HID + col]) =
                    make_float2(acc[m][n][2] + bb.x, acc[m][n][3] + bb.y);
            }
        }
    }
}

// ---------------------------------------------------------------------------
extern "C" void kernel_launch(void* const* d_in, const int* in_sizes, int n_in,
                              void* d_out, int out_size)
{
    const float* query = (const float*)d_in[0];
    const float* key   = (const float*)d_in[1];
    const float* value = (const float*)d_in[2];
    const int*   mask  = (const int*)  d_in[3];
    const float* Wq    = (const float*)d_in[4];
    const float* bq    = (const float*)d_in[5];
    const float* Wk    = (const float*)d_in[6];
    const float* bk    = (const float*)d_in[7];
    const float* Wv    = (const float*)d_in[8];
    const float* bv    = (const float*)d_in[9];
    const float* Wh    = (const float*)d_in[10];
    const float* bh    = (const float*)d_in[11];

    float* out     = (float*)d_out;                          // [B,S,HID]
    float* att_out = (float*)d_out + (size_t)MROWS * HID;    // [B,S,S]

    unsigned *pQt, *pKt, *pWt, *pVt, *pWhT;
    cudaGetSymbolAddress((void**)&pQt, g_Qt);
    cudaGetSymbolAddress((void**)&pKt, g_Kt);
    cudaGetSymbolAddress((void**)&pWt, g_Wt);
    cudaGetSymbolAddress((void**)&pVt, g_Vt);
    cudaGetSymbolAddress((void**)&pWhT, g_WhT);
    unsigned* pWtq = pWt;
    unsigned* pWtk = pWt + HID * HID;
    unsigned* pWtv = pWt + 2 * HID * HID;

    // All weight transposes in one launch
    transpose_all_kernel<<<160, 256>>>(Wq, Wk, Wv, Wh, pWtq, pWtk, pWtv, pWhT);

    // All three projections in ONE launch (A + W both via cp.async)
    size_t gsmem = (size_t)(2 * 128 * GS + 2 * 64 * GS) * sizeof(unsigned); // 55296
    cudaFuncSetAttribute(gemm_fused_kernel,
                         cudaFuncAttributeMaxDynamicSharedMemorySize, (int)gsmem);
    gemm_fused_kernel<<<dim3(9, MROWS / 128), 256, gsmem>>>(
        query, key, value, pWtq, pWtk, pWtv, bq, bk, bv, pQt, pKt, pVt);

    // Attention (round-8 proven version, frozen)
    size_t smem = (size_t)(32 * QS_ST + 2 * 256 * KS_ST) * sizeof(unsigned)
                  + 32 * 9 * sizeof(float);   // 173696 B
    cudaFuncSetAttribute(attn_kernel,
                         cudaFuncAttributeMaxDynamicSharedMemorySize, (int)smem);
    attn_kernel<<<dim3(SEQ / 32, BATCH), 256, smem>>>(pQt, pKt, mask, att_out);

    // ctx + output projection (round-12 proven version)
    size_t csmem = (size_t)(2 * 128 * CTS) * sizeof(unsigned);   // 69632 B
    cudaFuncSetAttribute(ctx_out_kernel,
                         cudaFuncAttributeMaxDynamicSharedMemorySize, (int)csmem);
    ctx_out_kernel<<<dim3(SEQ / 128, BATCH), 256, csmem>>>(
        att_out, pVt, pWhT, bh, out);
}

// round 17
// speedup vs baseline: 1.4111x; 1.0026x over previous
#include <cuda_runtime.h>
#include <cuda_bf16.h>
#include <math.h>

// Problem constants
#define BATCH   64
#define SEQ     512
#define HID     256
#define NHEADS  4
#define HDIM    64
#define MROWS   (BATCH*SEQ)      // 32768
#define C_EXP   0.18033688011112042f   // 0.125 * log2(e)

// Scratch (alloc-free rule: __device__ globals)
__device__ unsigned g_Qt[(size_t)MROWS * HID];                // Q proj tf32, row-major
__device__ unsigned g_Kt[(size_t)MROWS * HID];                // K proj tf32, [B][H][S][64]
__device__ unsigned g_Vt[(size_t)BATCH * HDIM * SEQ];         // V^T per batch, tf32
__device__ unsigned g_Wt[2 * HID * HID + HID * HDIM];         // Wq^T, Wk^T, Wv^T tf32
__device__ unsigned g_WhT[HID * HDIM];                        // Wh^T tf32 [256][64]

__device__ __forceinline__ unsigned f2tf32(float x)
{
    unsigned o;
    asm("cvt.rna.tf32.f32 %0, %1;" : "=r"(o) : "f"(x));
    return o;
}

__device__ __forceinline__ void cp16(void* dst_smem, const void* src_gmem)
{
    unsigned s = (unsigned)__cvta_generic_to_shared(dst_smem);
    asm volatile("cp.async.cg.shared.global [%0], [%1], 16;" :: "r"(s), "l"(src_gmem));
}
__device__ __forceinline__ void cp_commit()
{
    asm volatile("cp.async.commit_group;");
}
__device__ __forceinline__ void cp_wait0()
{
    asm volatile("cp.async.wait_group 0;");
}

// ---------------------------------------------------------------------------
// All four weight transposes in ONE kernel. 160 blocks of 32x32 tiles.
// ---------------------------------------------------------------------------
__global__ void __launch_bounds__(256)
transpose_all_kernel(const float* __restrict__ Wq, const float* __restrict__ Wk,
                     const float* __restrict__ Wv, const float* __restrict__ Wh,
                     unsigned* __restrict__ dq, unsigned* __restrict__ dk,
                     unsigned* __restrict__ dv, unsigned* __restrict__ dh)
{
    __shared__ unsigned t[32][33];
    int id = blockIdx.x;
    const float* src; unsigned* dst; int K, N, lid;
    if (id < 64)       { src = Wq; dst = dq; K = 256; N = 256; lid = id; }
    else if (id < 128) { src = Wk; dst = dk; K = 256; N = 256; lid = id - 64; }
    else if (id < 144) { src = Wv; dst = dv; K = 256; N = 64;  lid = id - 128; }
    else               { src = Wh; dst = dh; K = 64;  N = 256; lid = id - 144; }
    int kt = K / 32;
    int k0 = (lid % kt) * 32;
    int n0 = (lid / kt) * 32;
    const int tx = threadIdx.x & 31;
    const int ty = threadIdx.x >> 5;

    #pragma unroll
    for (int i = 0; i < 4; i++) {
        int r = ty + i * 8;
        t[tx][r] = f2tf32(src[(size_t)(k0 + r) * N + n0 + tx]);
    }
    __syncthreads();
    #pragma unroll
    for (int i = 0; i < 4; i++) {
        int r = ty + i * 8;
        dst[(size_t)(n0 + r) * K + k0 + tx] = t[r][tx];
    }
}

// ---------------------------------------------------------------------------
// FUSED projection GEMMs, 128x128 tiles for Q/K, 128x64 for V.
// grid.x = 5: 0..1 -> Q (n0 = bx*128), 2..3 -> K, 4 -> V.
// A staged via cp.async raw fp32 bits (tf32 mma truncates); W via cp.async.
// Wide path: warp tile 32x64 (2m x 8n of m16n8k8). Narrow (V): 32x32.
// smem: Asb 2x[128][36] + Wsb 2x[128][36] = 73728 B -> 2 CTAs/SM.
// ---------------------------------------------------------------------------
#define GS 36

__global__ void __launch_bounds__(256, 2)
gemm_fused_kernel(const float* __restrict__ Aq, const float* __restrict__ Ak,
                  const float* __restrict__ Av,
                  const unsigned* __restrict__ Wtq, const unsigned* __restrict__ Wtk,
                  const unsigned* __restrict__ Wtv,
                  const float* __restrict__ bq, const float* __restrict__ bk,
                  const float* __restrict__ bv,
                  unsigned* __restrict__ Qt, unsigned* __restrict__ Kt,
                  unsigned* __restrict__ Vt)
{
    extern __shared__ unsigned gsm[];
    unsigned* Asb[2] = { gsm, gsm + 128 * GS };
    unsigned* Wsb[2] = { gsm + 2 * 128 * GS, gsm + 3 * 128 * GS };

    const int bx = blockIdx.x;
    const float* A; const unsigned* Wt; const float* bias; unsigned* Ct;
    int tout, n0;
    if (bx < 2)      { A = Aq; Wt = Wtq; bias = bq; Ct = Qt; tout = 2; n0 = bx * 128; }
    else if (bx < 4) { A = Ak; Wt = Wtk; bias = bk; Ct = Kt; tout = 3; n0 = (bx - 2) * 128; }
    else             { A = Av; Wt = Wtv; bias = bv; Ct = Vt; tout = 1; n0 = 0; }

    const int m0  = blockIdx.y * 128;
    const int tid = threadIdx.x;
    const int w   = tid >> 5;
    const int tx  = tid & 31;
    const int lane4 = tx & 3;
    const int wq    = tx >> 2;
    const int mb = (w & 3) * 32;

    const int lr  = tid >> 3;          // stage row (0..31)
    const int lc4 = (tid & 7) * 4;     // col group *4

    #define CPA(kc, buf) do { \
        _Pragma("unroll") \
        for (int it = 0; it < 4; it++) \
            cp16(&Asb[buf][(lr + it * 32) * GS + lc4], \
                 &A[(size_t)(m0 + lr + it * 32) * 256 + (kc) * 32 + lc4]); \
    } while (0)
    #define CPW_WIDE(kc, buf) do { \
        _Pragma("unroll") \
        for (int it = 0; it < 4; it++) \
            cp16(&Wsb[buf][(lr + it * 32) * GS + lc4], \
                 &Wt[(size_t)(n0 + lr + it * 32) * 256 + (kc) * 32 + lc4]); \
    } while (0)
    #define CPW_NARROW(kc, buf) do { \
        _Pragma("unroll") \
        for (int it = 0; it < 2; it++) \
            cp16(&Wsb[buf][(lr + it * 32) * GS + lc4], \
                 &Wt[(size_t)(n0 + lr + it * 32) * 256 + (kc) * 32 + lc4]); \
    } while (0)

    if (tout != 1) {
        // ================= WIDE PATH (Q / K, N-tile = 128) =================
        const int nbw = (w >> 2) * 64;
        float acc[2][8][4];
        #pragma unroll
        for (int m = 0; m < 2; m++)
            #pragma unroll
            for (int n = 0; n < 8; n++)
                #pragma unroll
                for (int c = 0; c < 4; c++) acc[m][n][c] = 0.f;

        CPA(0, 0);
        CPW_WIDE(0, 0);
        cp_commit();
        cp_wait0();
        __syncthreads();

        #pragma unroll 1
        for (int kc8 = 0; kc8 < 8; kc8++) {
            int cur = kc8 & 1;
            if (kc8 < 7) {
                CPA(kc8 + 1, 1 - cur);
                CPW_WIDE(kc8 + 1, 1 - cur);
                cp_commit();
            }

            unsigned* As = Asb[cur];
            unsigned* Ws = Wsb[cur];
            #pragma unroll
            for (int kk = 0; kk < 4; kk++) {
                unsigned a[2][4], bf[8][2];
                #pragma unroll
                for (int m = 0; m < 2; m++) {
                    int row = mb + m * 16 + wq;
                    int col = kk * 8 + lane4;
                    a[m][0] = As[row * GS + col];
                    a[m][1] = As[(row + 8) * GS + col];
                    a[m][2] = As[row * GS + col + 4];
                    a[m][3] = As[(row + 8) * GS + col + 4];
                }
                #pragma unroll
                for (int n = 0; n < 8; n++) {
                    int nr = nbw + n * 8 + wq;
                    bf[n][0] = Ws[nr * GS + kk * 8 + lane4];
                    bf[n][1] = Ws[nr * GS + kk * 8 + lane4 + 4];
                }
                #pragma unroll
                for (int m = 0; m < 2; m++)
                    #pragma unroll
                    for (int n = 0; n < 8; n++) {
                        float* d = acc[m][n];
                        asm volatile(
                            "mma.sync.aligned.m16n8k8.row.col.f32.tf32.tf32.f32 "
                            "{%0,%1,%2,%3}, {%4,%5,%6,%7}, {%8,%9}, {%0,%1,%2,%3};\n"
                            : "+f"(d[0]), "+f"(d[1]), "+f"(d[2]), "+f"(d[3])
                            : "r"(a[m][0]), "r"(a[m][1]), "r"(a[m][2]), "r"(a[m][3]),
                              "r"(bf[n][0]), "r"(bf[n][1]));
                    }
            }

            if (kc8 < 7) {
                cp_wait0();
                __syncthreads();
            }
        }

        if (tout == 2) {
            // Qt: flat [M][256]
            #pragma unroll
            for (int m = 0; m < 2; m++) {
                int row = m0 + mb + m * 16 + wq;
                #pragma unroll
                for (int n = 0; n < 8; n++) {
                    int col = n0 + nbw + n * 8 + lane4 * 2;
                    float2 bb = *reinterpret_cast<const float2*>(&bias[col]);
                    Ct[(size_t)row * HID + col]           = f2tf32(acc[m][n][0] + bb.x);
                    Ct[(size_t)row * HID + col + 1]       = f2tf32(acc[m][n][1] + bb.y);
                    Ct[(size_t)(row + 8) * HID + col]     = f2tf32(acc[m][n][2] + bb.x);
                    Ct[(size_t)(row + 8) * HID + col + 1] = f2tf32(acc[m][n][3] + bb.y);
                }
            }
        } else {
            // Kt: [b][h][s][d]
            #pragma unroll
            for (int m = 0; m < 2; m++) {
                int r0 = m0 + mb + m * 16 + wq;
                int r1 = r0 + 8;
                int bb0 = r0 >> 9, s0 = r0 & 511, s1 = r1 & 511;
                #pragma unroll
                for (int n = 0; n < 8; n++) {
                    int col = n0 + nbw + n * 8 + lane4 * 2;
                    int h = col >> 6, d = col & 63;
                    size_t base = ((size_t)bb0 * NHEADS + h) * SEQ;
                    float2 bb = *reinterpret_cast<const float2*>(&bias[col]);
                    Ct[(base + s0) * HDIM + d]     = f2tf32(acc[m][n][0] + bb.x);
                    Ct[(base + s0) * HDIM + d + 1] = f2tf32(acc[m][n][1] + bb.y);
                    Ct[(base + s1) * HDIM + d]     = f2tf32(acc[m][n][2] + bb.x);
                    Ct[(base + s1) * HDIM + d + 1] = f2tf32(acc[m][n][3] + bb.y);
                }
            }
        }
    } else {
        // ================= NARROW PATH (V, N-tile = 64) =================
        const int nb = (w >> 2) * 32;
        float acc[2][4][4];
        #pragma unroll
        for (int m = 0; m < 2; m++)
            #pragma unroll
            for (int n = 0; n < 4; n++)
                #pragma unroll
                for (int c = 0; c < 4; c++) acc[m][n][c] = 0.f;

        CPA(0, 0);
        CPW_NARROW(0, 0);
        cp_commit();
        cp_wait0();
        __syncthreads();

        #pragma unroll 1
        for (int kc8 = 0; kc8 < 8; kc8++) {
            int cur = kc8 & 1;
            if (kc8 < 7) {
                CPA(kc8 + 1, 1 - cur);
                CPW_NARROW(kc8 + 1, 1 - cur);
                cp_commit();
            }

            unsigned* As = Asb[cur];
            unsigned* Ws = Wsb[cur];
            #pragma unroll
            for (int kk = 0; kk < 4; kk++) {
                unsigned a[2][4], bf[4][2];
                #pragma unroll
                for (int m = 0; m < 2; m++) {
                    int row = mb + m * 16 + wq;
                    int col = kk * 8 + lane4;
                    a[m][0] = As[row * GS + col];
                    a[m][1] = As[(row + 8) * GS + col];
                    a[m][2] = As[row * GS + col + 4];
                    a[m][3] = As[(row + 8) * GS + col + 4];
                }
                #pragma unroll
                for (int n = 0; n < 4; n++) {
                    int nr = nb + n * 8 + wq;
                    bf[n][0] = Ws[nr * GS + kk * 8 + lane4];
                    bf[n][1] = Ws[nr * GS + kk * 8 + lane4 + 4];
                }
                #pragma unroll
                for (int m = 0; m < 2; m++)
                    #pragma unroll
                    for (int n = 0; n < 4; n++) {
                        float* d = acc[m][n];
                        asm volatile(
                            "mma.sync.aligned.m16n8k8.row.col.f32.tf32.tf32.f32 "
                            "{%0,%1,%2,%3}, {%4,%5,%6,%7}, {%8,%9}, {%0,%1,%2,%3};\n"
                            : "+f"(d[0]), "+f"(d[1]), "+f"(d[2]), "+f"(d[3])
                            : "r"(a[m][0]), "r"(a[m][1]), "r"(a[m][2]), "r"(a[m][3]),
                              "r"(bf[n][0]), "r"(bf[n][1]));
                    }
            }

            if (kc8 < 7) {
                cp_wait0();
                __syncthreads();
            }
        }

        // Vt: [b][n][s]
        #pragma unroll
        for (int m = 0; m < 2; m++) {
            int r0 = m0 + mb + m * 16 + wq;
            int r1 = r0 + 8;
            int b0 = r0 >> 9, s0 = r0 & 511;
            int s1 = r1 & 511;
            #pragma unroll
            for (int n = 0; n < 4; n++) {
                int col = nb + n * 8 + lane4 * 2;
                float2 bb = *reinterpret_cast<const float2*>(&bias[col]);
                Ct[((size_t)b0 * HDIM + col) * SEQ + s0]     = f2tf32(acc[m][n][0] + bb.x);
                Ct[((size_t)b0 * HDIM + col + 1) * SEQ + s0] = f2tf32(acc[m][n][1] + bb.y);
                Ct[((size_t)b0 * HDIM + col) * SEQ + s1]     = f2tf32(acc[m][n][2] + bb.x);
                Ct[((size_t)b0 * HDIM + col + 1) * SEQ + s1] = f2tf32(acc[m][n][3] + bb.y);
            }
        }
    }
    #undef CPA
    #undef CPW_WIDE
    #undef CPW_NARROW
}

// ---------------------------------------------------------------------------
// Slim exp2: no clamp (inputs bounded), 2-op exponent reconstruction.
// ---------------------------------------------------------------------------
__device__ __forceinline__ float exp2s(float y)
{
    float t = y + 12582912.0f;
    float f = y - (t - 12582912.0f);
    float p = 0.0013333558f;
    p = fmaf(p, f, 0.0096181291f);
    p = fmaf(p, f, 0.0555041087f);
    p = fmaf(p, f, 0.2402265069f);
    p = fmaf(p, f, 0.6931471806f);
    p = fmaf(p, f, 1.0f);
    unsigned r = (__float_as_uint(t) << 23) + 0x3F800000u;
    return __uint_as_float(r) * p;
}

// ---------------------------------------------------------------------------
// Attention kernel (round-8/12 proven version, FROZEN).
// ---------------------------------------------------------------------------
#define QS_ST 260
#define KS_ST 68

__global__ void __launch_bounds__(256)
attn_kernel(const unsigned* __restrict__ Qt, const unsigned* __restrict__ Kt,
            const int* __restrict__ mask, float* __restrict__ att_out)
{
    extern __shared__ unsigned smu[];
    unsigned* Qs = smu;                              // [32][260]
    unsigned* Ksb[2] = { smu + 32 * QS_ST,
                         smu + 32 * QS_ST + 256 * KS_ST };   // 2 x [256][68]
    float* red = (float*)(smu + 32 * QS_ST + 2 * 256 * KS_ST);  // [32][9]

    const int b   = blockIdx.y;
    const int q0  = blockIdx.x * 32;
    const int tid = threadIdx.x;
    const int w   = tid >> 5;
    const int tx  = tid & 31;
    const int lane4 = tx & 3;
    const int wq    = tx >> 2;

    {
        const unsigned* src = &Kt[(((size_t)b * NHEADS + 0) * SEQ + 0) * HDIM];
        #pragma unroll
        for (int it = 0; it < 16; it++) {
            int idx = it * 256 + tid;
            int row = idx >> 4;
            int c4  = (idx & 15) * 4;
            cp16(&Ksb[0][row * KS_ST + c4], &src[row * HDIM + c4]);
        }
        cp_commit();
    }

    #pragma unroll
    for (int it = 0; it < 8; it++) {
        int idx = it * 256 + tid;
        int q   = idx >> 6;
        int c4  = (idx & 63) * 4;
        uint4 v = *reinterpret_cast<const uint4*>(
            &Qt[(size_t)(b * SEQ + q0 + q) * HID + c4]);
        *reinterpret_cast<uint4*>(&Qs[q * QS_ST + c4]) = v;
    }

    unsigned long long mbits = 0ull;
    #pragma unroll
    for (int rs = 0; rs < 4; rs++) {
        int row = (rs >> 1) * 16 + (rs & 1) * 8 + wq;
        const int* mrow = mask + ((size_t)b * SEQ + q0 + row) * SEQ;
        #pragma unroll
        for (int nt = 0; nt < 8; nt++) {
            int2 mv = *reinterpret_cast<const int2*>(&mrow[nt * 64 + w * 8 + lane4 * 2]);
            int bi = rs * 16 + nt * 2;
            mbits |= ((unsigned long long)(mv.x != 0)) << bi;
            mbits |= ((unsigned long long)(mv.y != 0)) << (bi + 1);
        }
    }

    float att_acc[64];
    #pragma unroll
    for (int i = 0; i < 64; i++) att_acc[i] = 0.f;

    cp_wait0();
    __syncthreads();

    float acc[64];

    #pragma unroll 1
    for (int h = 0; h < NHEADS; h++) {
        {
            const unsigned* src = &Kt[(((size_t)b * NHEADS + h) * SEQ + 256) * HDIM];
            #pragma unroll
            for (int it = 0; it < 16; it++) {
                int idx = it * 256 + tid;
                int row = idx >> 4;
                int c4  = (idx & 15) * 4;
                cp16(&Ksb[1][row * KS_ST + c4], &src[row * HDIM + c4]);
            }
            cp_commit();
        }
        #pragma unroll
        for (int i = 0; i < 64; i++) acc[i] = 0.f;

        #pragma unroll
        for (int ks = 0; ks < 8; ks++) {
            unsigned a[2][4];
            #pragma unroll
            for (int m = 0; m < 2; m++) {
                int row = m * 16 + wq;
                int cb  = h * 64 + ks * 8 + lane4;
                a[m][0] = Qs[row * QS_ST + cb];
                a[m][1] = Qs[(row + 8) * QS_ST + cb];
                a[m][2] = Qs[row * QS_ST + cb + 4];
                a[m][3] = Qs[(row + 8) * QS_ST + cb + 4];
            }
            #pragma unroll
            for (int ntl = 0; ntl < 4; ntl++) {
                int krow = ntl * 64 + w * 8 + wq;
                unsigned b0 = Ksb[0][krow * KS_ST + ks * 8 + lane4];
                unsigned b1 = Ksb[0][krow * KS_ST + ks * 8 + lane4 + 4];
                #pragma unroll
                for (int m = 0; m < 2; m++) {
                    float* d = &acc[(m * 8 + ntl) * 4];
                    asm volatile(
                        "mma.sync.aligned.m16n8k8.row.col.f32.tf32.tf32.f32 "
                        "{%0,%1,%2,%3}, {%4,%5,%6,%7}, {%8,%9}, {%0,%1,%2,%3};\n"
                        : "+f"(d[0]), "+f"(d[1]), "+f"(d[2]), "+f"(d[3])
                        : "r"(a[m][0]), "r"(a[m][1]), "r"(a[m][2]), "r"(a[m][3]),
                          "r"(b0), "r"(b1));
                }
            }
        }
        cp_wait0();
        __syncthreads();

        if (h < NHEADS - 1) {
            const unsigned* src = &Kt[(((size_t)b * NHEADS + h + 1) * SEQ) * HDIM];
            #pragma unroll
            for (int it = 0; it < 16; it++) {
                int idx = it * 256 + tid;
                int row = idx >> 4;
                int c4  = (idx & 15) * 4;
                cp16(&Ksb[0][row * KS_ST + c4], &src[row * HDIM + c4]);
            }
            cp_commit();
        }

        #pragma unroll
        for (int ks = 0; ks < 8; ks++) {
            unsigned a[2][4];
            #pragma unroll
            for (int m = 0; m < 2; m++) {
                int row = m * 16 + wq;
                int cb  = h * 64 + ks * 8 + lane4;
                a[m][0] = Qs[row * QS_ST + cb];
                a[m][1] = Qs[(row + 8) * QS_ST + cb];
                a[m][2] = Qs[row * QS_ST + cb + 4];
                a[m][3] = Qs[(row + 8) * QS_ST + cb + 4];
            }
            #pragma unroll
            for (int ntl = 0; ntl < 4; ntl++) {
                int krow = ntl * 64 + w * 8 + wq;
                unsigned b0 = Ksb[1][krow * KS_ST + ks * 8 + lane4];
                unsigned b1 = Ksb[1][krow * KS_ST + ks * 8 + lane4 + 4];
                #pragma unroll
                for (int m = 0; m < 2; m++) {
                    float* d = &acc[(m * 8 + 4 + ntl) * 4];
                    asm volatile(
                        "mma.sync.aligned.m16n8k8.row.col.f32.tf32.tf32.f32 "
                        "{%0,%1,%2,%3}, {%4,%5,%6,%7}, {%8,%9}, {%0,%1,%2,%3};\n"
                        : "+f"(d[0]), "+f"(d[1]), "+f"(d[2]), "+f"(d[3])
                        : "r"(a[m][0]), "r"(a[m][1]), "r"(a[m][2]), "r"(a[m][3]),
                          "r"(b0), "r"(b1));
                }
            }
        }

        float rsum[4];
        #pragma unroll
        for (int rs = 0; rs < 4; rs++) {
            int m = rs >> 1, cb2 = (rs & 1) * 2;
            float s = 0.f;
            #pragma unroll
            for (int nt = 0; nt < 8; nt++)
                #pragma unroll
                for (int p = 0; p < 2; p++) {
                    int id = (m * 8 + nt) * 4 + cb2 + p;
                    int bi = rs * 16 + nt * 2 + p;
                    float e = exp2s(acc[id] * C_EXP);
                    e = ((mbits >> bi) & 1ull) ? e : 0.f;
                    acc[id] = e;
                    s += e;
                }
            s += __shfl_xor_sync(0xffffffffu, s, 1);
            s += __shfl_xor_sync(0xffffffffu, s, 2);
            rsum[rs] = s;
        }
        if (lane4 == 0) {
            #pragma unroll
            for (int rs = 0; rs < 4; rs++) {
                int row = (rs >> 1) * 16 + (rs & 1) * 8 + wq;
                red[row * 9 + w] = rsum[rs];
            }
        }
        __syncthreads();
        #pragma unroll
        for (int rs = 0; rs < 4; rs++) {
            int row = (rs >> 1) * 16 + (rs & 1) * 8 + wq;
            float s = 0.f;
            #pragma unroll
            for (int ww = 0; ww < 8; ww++) s += red[row * 9 + ww];
            float inv = 0.25f / s;
            int m = rs >> 1, cb2 = (rs & 1) * 2;
            #pragma unroll
            for (int nt = 0; nt < 8; nt++)
                #pragma unroll
                for (int p = 0; p < 2; p++) {
                    int id = (m * 8 + nt) * 4 + cb2 + p;
                    att_acc[id] += acc[id] * inv;
                }
        }
        if (h < NHEADS - 1) {
            cp_wait0();
            __syncthreads();
        }
    }

    #pragma unroll
    for (int rs = 0; rs < 4; rs++) {
        int row = (rs >> 1) * 16 + (rs & 1) * 8 + wq;
        int m = rs >> 1, cb2 = (rs & 1) * 2;
        float* dst = att_out + ((size_t)b * SEQ + q0 + row) * SEQ;
        #pragma unroll
        for (int nt = 0; nt < 8; nt++) {
            int col = nt * 64 + w * 8 + lane4 * 2;
            *reinterpret_cast<float2*>(&dst[col]) =
                make_float2(att_acc[(m * 8 + nt) * 4 + cb2],
                            att_acc[(m * 8 + nt) * 4 + cb2 + 1]);
        }
    }
}

// ---------------------------------------------------------------------------
// ctx + out-proj, tf32 tensor cores (round-12 proven version, 2 CTAs/SM).
// ---------------------------------------------------------------------------
#define CTS 68

__global__ void __launch_bounds__(256, 2)
ctx_out_kernel(const float* __restrict__ att, const unsigned* __restrict__ Vt,
               const unsigned* __restrict__ WhT, const float* __restrict__ bh,
               float* __restrict__ out)
{
    extern __shared__ unsigned cs[];
    unsigned* As = cs;                 // [128][68]
    unsigned* Bs = cs + 128 * CTS;     // [128][68]

    const int b   = blockIdx.y;
    const int q0  = blockIdx.x * 128;
    const int tid = threadIdx.x;
    const int w   = tid >> 5;
    const int tx  = tid & 31;
    const int lane4 = tx & 3;
    const int wq    = tx >> 2;
    const int mb = (w & 3) * 32;

    const int nb1 = (w >> 2) * 32;
    float ctx_acc[2][4][4];
    #pragma unroll
    for (int m = 0; m < 2; m++)
        #pragma unroll
        for (int n = 0; n < 4; n++)
            #pragma unroll
            for (int c = 0; c < 4; c++) ctx_acc[m][n][c] = 0.f;

    for (int kc = 0; kc < 8; kc++) {
        __syncthreads();
        #pragma unroll
        for (int it = 0; it < 8; it++) {
            int idx = it * 256 + tid;
            int q   = idx >> 4;
            int c4  = (idx & 15) * 4;
            float4 v = *reinterpret_cast<const float4*>(
                &att[((size_t)(b * SEQ) + q0 + q) * SEQ + kc * 64 + c4]);
            *reinterpret_cast<uint4*>(&As[q * CTS + c4]) =
                make_uint4(f2tf32(v.x), f2tf32(v.y), f2tf32(v.z), f2tf32(v.w));
        }
        #pragma unroll
        for (int it = 0; it < 4; it++) {
            int idx = it * 256 + tid;
            int d   = idx >> 4;
            int c4  = (idx & 15) * 4;
            uint4 v = *reinterpret_cast<const uint4*>(
                &Vt[((size_t)b * HDIM + d) * SEQ + kc * 64 + c4]);
            *reinterpret_cast<uint4*>(&Bs[d * CTS + c4]) = v;
        }
        __syncthreads();

        #pragma unroll
        for (int kk = 0; kk < 8; kk++) {
            unsigned a[2][4], bf[4][2];
            #pragma unroll
            for (int m = 0; m < 2; m++) {
                int row = mb + m * 16 + wq;
                int col = kk * 8 + lane4;
                a[m][0] = As[row * CTS + col];
                a[m][1] = As[(row + 8) * CTS + col];
                a[m][2] = As[row * CTS + col + 4];
                a[m][3] = As[(row + 8) * CTS + col + 4];
            }
            #pragma unroll
            for (int n = 0; n < 4; n++) {
                int nr = nb1 + n * 8 + wq;
                bf[n][0] = Bs[nr * CTS + kk * 8 + lane4];
                bf[n][1] = Bs[nr * CTS + kk * 8 + lane4 + 4];
            }
            #pragma unroll
            for (int m = 0; m < 2; m++)
                #pragma unroll
                for (int n = 0; n < 4; n++) {
                    float* d = ctx_acc[m][n];
                    asm volatile(
                        "mma.sync.aligned.m16n8k8.row.col.f32.tf32.tf32.f32 "
                        "{%0,%1,%2,%3}, {%4,%5,%6,%7}, {%8,%9}, {%0,%1,%2,%3};\n"
                        : "+f"(d[0]), "+f"(d[1]), "+f"(d[2]), "+f"(d[3])
                        : "r"(a[m][0]), "r"(a[m][1]), "r"(a[m][2]), "r"(a[m][3]),
                          "r"(bf[n][0]), "r"(bf[n][1]));
                }
        }
    }

    __syncthreads();
    #pragma unroll
    for (int m = 0; m < 2; m++) {
        int row = mb + m * 16 + wq;
        #pragma unroll
        for (int n = 0; n < 4; n++) {
            int col = nb1 + n * 8 + lane4 * 2;
            As[row * CTS + col]           = f2tf32(ctx_acc[m][n][0]);
            As[row * CTS + col + 1]       = f2tf32(ctx_acc[m][n][1]);
            As[(row + 8) * CTS + col]     = f2tf32(ctx_acc[m][n][2]);
            As[(row + 8) * CTS + col + 1] = f2tf32(ctx_acc[m][n][3]);
        }
    }

    const int nb2 = (w >> 2) * 64;
    for (int p = 0; p < 2; p++) {
        __syncthreads();
        #pragma unroll
        for (int it = 0; it < 8; it++) {
            int idx = it * 256 + tid;
            int r   = idx >> 4;
            int c4  = (idx & 15) * 4;
            uint4 v = *reinterpret_cast<const uint4*>(
                &WhT[(size_t)(p * 128 + r) * HDIM + c4]);
            *reinterpret_cast<uint4*>(&Bs[r * CTS + c4]) = v;
        }
        __syncthreads();

        float acc[2][8][4];
        #pragma unroll
        for (int m = 0; m < 2; m++)
            #pragma unroll
            for (int n = 0; n < 8; n++)
                #pragma unroll
                for (int c = 0; c < 4; c++) acc[m][n][c] = 0.f;

        #pragma unroll
        for (int kk = 0; kk < 8; kk++) {
            unsigned a[2][4], bf[8][2];
            #pragma unroll
            for (int m = 0; m < 2; m++) {
                int row = mb + m * 16 + wq;
                int col = kk * 8 + lane4;
                a[m][0] = As[row * CTS + col];
                a[m][1] = As[(row + 8) * CTS + col];
                a[m][2] = As[row * CTS + col + 4];
                a[m][3] = As[(row + 8) * CTS + col + 4];
            }
            #pragma unroll
            for (int n = 0; n < 8; n++) {
                int nr = nb2 + n * 8 + wq;
                bf[n][0] = Bs[nr * CTS + kk * 8 + lane4];
                bf[n][1] = Bs[nr * CTS + kk * 8 + lane4 + 4];
            }
            #pragma unroll
            for (int m = 0; m < 2; m++)
                #pragma unroll
                for (int n = 0; n < 8; n++) {
                    float* d = acc[m][n];
                    asm volatile(
                        "mma.sync.aligned.m16n8k8.row.col.f32.tf32.tf32.f32 "
                        "{%0,%1,%2,%3}, {%4,%5,%6,%7}, {%8,%9}, {%0,%1,%2,%3};\n"
                        : "+f"(d[0]), "+f"(d[1]), "+f"(d[2]), "+f"(d[3])
                        : "r"(a[m][0]), "r"(a[m][1]), "r"(a[m][2]), "r"(a[m][3]),
                          "r"(bf[n][0]), "r"(bf[n][1]));
                }
        }

        #pragma unroll
        for (int m = 0; m < 2; m++) {
            int row = q0 + mb + m * 16 + wq;
            #pragma unroll
            for (int n = 0; n < 8; n++) {
                int col = p * 128 + nb2 + n * 8 + lane4 * 2;
                float2 bb = *reinterpret_cast<const float2*>(&bh[col]);
                *reinterpret_cast<float2*>(
                    &out[((size_t)(b * SEQ) + row) * HID + col]) =
                    make_float2(acc[m][n][0] + bb.x, acc[m][n][1] + bb.y);
                *reinterpret_cast<float2*>(
                    &out[((size_t)(b * SEQ) + row + 8) * HID + col]) =
                    make_float2(acc[m][n][2] + bb.x, acc[m][n][3] + bb.y);
            }
        }
    }
}

// ---------------------------------------------------------------------------
extern "C" void kernel_launch(void* const* d_in, const int* in_sizes, int n_in,
                              void* d_out, int out_size)
{
    const float* query = (const float*)d_in[0];
    const float* key   = (const float*)d_in[1];
    const float* value = (const float*)d_in[2];
    const int*   mask  = (const int*)  d_in[3];
    const float* Wq    = (const float*)d_in[4];
    const float* bq    = (const float*)d_in[5];
    const float* Wk    = (const float*)d_in[6];
    const float* bk    = (const float*)d_in[7];
    const float* Wv    = (const float*)d_in[8];
    const float* bv    = (const float*)d_in[9];
    const float* Wh    = (const float*)d_in[10];
    const float* bh    = (const float*)d_in[11];

    float* out     = (float*)d_out;                          // [B,S,HID]
    float* att_out = (float*)d_out + (size_t)MROWS * HID;    // [B,S,S]

    unsigned *pQt, *pKt, *pWt, *pVt, *pWhT;
    cudaGetSymbolAddress((void**)&pQt, g_Qt);
    cudaGetSymbolAddress((void**)&pKt, g_Kt);
    cudaGetSymbolAddress((void**)&pWt, g_Wt);
    cudaGetSymbolAddress((void**)&pVt, g_Vt);
    cudaGetSymbolAddress((void**)&pWhT, g_WhT);
    unsigned* pWtq = pWt;
    unsigned* pWtk = pWt + HID * HID;
    unsigned* pWtv = pWt + 2 * HID * HID;

    // All weight transposes in one launch
    transpose_all_kernel<<<160, 256>>>(Wq, Wk, Wv, Wh, pWtq, pWtk, pWtv, pWhT);

    // All three projections in ONE launch (128x128 tiles for Q/K)
    size_t gsmem = (size_t)(4 * 128 * GS) * sizeof(unsigned);   // 73728 B
    cudaFuncSetAttribute(gemm_fused_kernel,
                         cudaFuncAttributeMaxDynamicSharedMemorySize, (int)gsmem);
    gemm_fused_kernel<<<dim3(5, MROWS / 128), 256, gsmem>>>(
        query, key, value, pWtq, pWtk, pWtv, bq, bk, bv, pQt, pKt, pVt);

    // Attention (round-8 proven version, frozen)
    size_t smem = (size_t)(32 * QS_ST + 2 * 256 * KS_ST) * sizeof(unsigned)
                  + 32 * 9 * sizeof(float);   // 173696 B
    cudaFuncSetAttribute(attn_kernel,
                         cudaFuncAttributeMaxDynamicSharedMemorySize, (int)smem);
    attn_kernel<<<dim3(SEQ / 32, BATCH), 256, smem>>>(pQt, pKt, mask, att_out);

    // ctx + output projection (round-12 proven version)
    size_t csmem = (size_t)(2 * 128 * CTS) * sizeof(unsigned);   // 69632 B
    cudaFuncSetAttribute(ctx_out_kernel,
                         cudaFuncAttributeMaxDynamicSharedMemorySize, (int)csmem);
    ctx_out_kernel<<<dim3(SEQ / 128, BATCH), 256, csmem>>>(
        att_out, pVt, pWhT, bh, out);
}